// round 1
// baseline (speedup 1.0000x reference)
#include <cuda_runtime.h>
#include <cuda_bf16.h>
#include <cstddef>

// Problem constants
#define BB 2
#define LL 384
#define DD 256
#define HH 8
#define DH 32

// ---------------- scratch (device globals; no allocation allowed) ----------------
__device__ float g_kproj[BB*HH*LL*DH];            // [b,h,l,dh]
__device__ float g_vproj[BB*HH*LL*DH];
__device__ float g_qu   [BB*HH*LL*DH];            // q + u
__device__ float g_qv   [BB*HH*LL*DH];            // q + v
__device__ float g_w    [(size_t)BB*HH*LL*DD];    // [b,h,q,din]
__device__ float g_bias [BB*HH*LL];               // [b,h,q]
__device__ float g_ac   [(size_t)BB*HH*LL*LL];    // A_C scores [b,h,q,k]
__device__ float g_scores[(size_t)BB*HH*LL*LL];   // final scores [b,h,q,k]

// ---------------- kernel 1: QKV projections (x @ W.T + b), remap to [b,h,l,dh] --
// grid (12,4), 256 threads. 64x64 tile, K-chunks of 32, 4x4 microtile.
__global__ __launch_bounds__(256) void proj_kernel(
    const float* __restrict__ x, const float* __restrict__ W,
    const float* __restrict__ bias, int mode,
    const float* __restrict__ uvec, const float* __restrict__ vvec)
{
    __shared__ float As[64][33];
    __shared__ float Bs[32][68];
    int m0 = blockIdx.x * 64, n0 = blockIdx.y * 64;
    int tid = threadIdx.x;
    int tx = tid & 15, ty = tid >> 4;
    float acc[4][4];
#pragma unroll
    for (int i = 0; i < 4; i++)
#pragma unroll
        for (int j = 0; j < 4; j++) acc[i][j] = 0.f;

    for (int k0 = 0; k0 < DD; k0 += 32) {
        for (int idx = tid; idx < 2048; idx += 256) {
            int r = idx >> 5, c = idx & 31;
            As[r][c] = x[(m0 + r) * DD + k0 + c];
        }
        for (int idx = tid; idx < 2048; idx += 256) {
            int n = idx >> 5, kk = idx & 31;
            Bs[kk][n] = W[(n0 + n) * DD + k0 + kk];
        }
        __syncthreads();
#pragma unroll
        for (int kk = 0; kk < 32; kk++) {
            float a0 = As[ty*4+0][kk], a1 = As[ty*4+1][kk];
            float a2 = As[ty*4+2][kk], a3 = As[ty*4+3][kk];
            float4 bb = *(const float4*)&Bs[kk][tx*4];
            acc[0][0] += a0*bb.x; acc[0][1] += a0*bb.y; acc[0][2] += a0*bb.z; acc[0][3] += a0*bb.w;
            acc[1][0] += a1*bb.x; acc[1][1] += a1*bb.y; acc[1][2] += a1*bb.z; acc[1][3] += a1*bb.w;
            acc[2][0] += a2*bb.x; acc[2][1] += a2*bb.y; acc[2][2] += a2*bb.z; acc[2][3] += a2*bb.w;
            acc[3][0] += a3*bb.x; acc[3][1] += a3*bb.y; acc[3][2] += a3*bb.z; acc[3][3] += a3*bb.w;
        }
        __syncthreads();
    }
#pragma unroll
    for (int i = 0; i < 4; i++) {
        int m = m0 + ty*4 + i;
        int b = m / LL, l = m - b * LL;
#pragma unroll
        for (int j = 0; j < 4; j++) {
            int n = n0 + tx*4 + j;
            int h = n >> 5, dh = n & 31;
            float val = acc[i][j] + bias[n];
            size_t o = (((size_t)b * HH + h) * LL + l) * DH + dh;
            if (mode == 0)      g_kproj[o] = val;
            else if (mode == 2) g_vproj[o] = val;
            else { g_qu[o] = val + uvec[n]; g_qv[o] = val + vvec[n]; }
        }
    }
}

// ---------------- kernel 2: w[b,h,q,:] = qv[b,h,q,:] @ Wr_h ; bias = qv . br_h --
// grid (B*H, 4), 256 threads; 96 q per CTA.
__global__ __launch_bounds__(256) void wproj_kernel(
    const float* __restrict__ Wr, const float* __restrict__ br)
{
    int bh = blockIdx.x;
    int h  = bh & (HH - 1);
    int q0 = blockIdx.y * 96;
    __shared__ float Wr_s[32][257];
    __shared__ float qv_s[32];
    __shared__ float br_s[32];
    int tid = threadIdx.x;
    for (int idx = tid; idx < 32 * 256; idx += 256) {
        int r = idx >> 8, c = idx & 255;
        Wr_s[r][c] = Wr[(h * DH + r) * DD + c];
    }
    if (tid < 32) br_s[tid] = br[h * DH + tid];
    __syncthreads();
    for (int qq = 0; qq < 96; qq++) {
        int q = q0 + qq;
        if (tid < 32) qv_s[tid] = g_qv[((size_t)bh * LL + q) * DH + tid];
        __syncthreads();
        float s = 0.f;
#pragma unroll
        for (int dh = 0; dh < 32; dh++) s += qv_s[dh] * Wr_s[dh][tid];
        g_w[((size_t)bh * LL + q) * DD + tid] = s;
        if (tid < 32) {
            float p = qv_s[tid] * br_s[tid];
#pragma unroll
            for (int o = 16; o; o >>= 1) p += __shfl_xor_sync(0xffffffffu, p, o);
            if (tid == 0) g_bias[bh * LL + q] = p;
        }
        __syncthreads();
    }
}

// ---------------- kernel 3: A_C[b,h,q,k] = (q+u) . k  (batched 384x384x32) -------
// grid (B*H, 6, 6), 256 threads. 64x64 tile, single K chunk of 32.
__global__ __launch_bounds__(256) void ac_kernel()
{
    __shared__ float As[64][33];
    __shared__ float Bs[32][68];
    int bh = blockIdx.x;
    int q0 = blockIdx.y * 64, k0 = blockIdx.z * 64;
    int tid = threadIdx.x, tx = tid & 15, ty = tid >> 4;
    for (int idx = tid; idx < 2048; idx += 256) {
        int r = idx >> 5, c = idx & 31;
        As[r][c] = g_qu[(size_t)bh * (LL * DH) + (q0 + r) * DH + c];
    }
    for (int idx = tid; idx < 2048; idx += 256) {
        int n = idx >> 5, d = idx & 31;
        Bs[d][n] = g_kproj[(size_t)bh * (LL * DH) + (k0 + n) * DH + d];
    }
    __syncthreads();
    float acc[4][4];
#pragma unroll
    for (int i = 0; i < 4; i++)
#pragma unroll
        for (int j = 0; j < 4; j++) acc[i][j] = 0.f;
#pragma unroll
    for (int d = 0; d < 32; d++) {
        float a0 = As[ty*4+0][d], a1 = As[ty*4+1][d];
        float a2 = As[ty*4+2][d], a3 = As[ty*4+3][d];
        float4 bb = *(const float4*)&Bs[d][tx*4];
        acc[0][0] += a0*bb.x; acc[0][1] += a0*bb.y; acc[0][2] += a0*bb.z; acc[0][3] += a0*bb.w;
        acc[1][0] += a1*bb.x; acc[1][1] += a1*bb.y; acc[1][2] += a1*bb.z; acc[1][3] += a1*bb.w;
        acc[2][0] += a2*bb.x; acc[2][1] += a2*bb.y; acc[2][2] += a2*bb.z; acc[2][3] += a2*bb.w;
        acc[3][0] += a3*bb.x; acc[3][1] += a3*bb.y; acc[3][2] += a3*bb.z; acc[3][3] += a3*bb.w;
    }
#pragma unroll
    for (int i = 0; i < 4; i++)
#pragma unroll
        for (int j = 0; j < 4; j++)
            g_ac[(size_t)bh * (LL * LL) + (size_t)(q0 + ty*4 + i) * LL + (k0 + tx*4 + j)]
                = acc[i][j];
}

// ---------------- kernel 4 (DOMINANT): stream pos, produce final scores ----------
// score[b,h,q,k] = (pos[b,q,k,:].w[b,h,q,:] + A_C + bias) * scale - (1-mask)*1e15
// grid (B*L), 256 threads (8 warps). Warp handles k = warp, warp+8, ...
__global__ __launch_bounds__(256) void score_kernel(
    const float* __restrict__ pos, const float* __restrict__ key_mask)
{
    int bq = blockIdx.x;
    int b = bq / LL, q = bq - b * LL;
    __shared__ float a_s[HH][LL];
    __shared__ float bias_s[HH];
    __shared__ float mask_s[LL];
    int tid = threadIdx.x;
    for (int idx = tid; idx < HH * LL; idx += 256) {
        int h = idx / LL, k = idx - h * LL;
        a_s[h][k] = g_ac[(size_t)(b * HH + h) * (LL * LL) + (size_t)q * LL + k];
    }
    if (tid < HH) bias_s[tid] = g_bias[(b * HH + tid) * LL + q];
    for (int idx = tid; idx < LL; idx += 256) mask_s[idx] = key_mask[b * LL + idx];

    int warp = tid >> 5, lane = tid & 31;
    // per-lane registers: w[h][din], din = lane*8 .. lane*8+7
    float wreg[8][8];
#pragma unroll
    for (int h = 0; h < 8; h++) {
        const float4* wp = (const float4*)(g_w + (((size_t)(b * HH + h)) * LL + q) * DD) + lane * 2;
        float4 w0 = wp[0], w1 = wp[1];
        wreg[h][0]=w0.x; wreg[h][1]=w0.y; wreg[h][2]=w0.z; wreg[h][3]=w0.w;
        wreg[h][4]=w1.x; wreg[h][5]=w1.y; wreg[h][6]=w1.z; wreg[h][7]=w1.w;
    }
    __syncthreads();

    const float scale = 0.17677669529663687f; // 1/sqrt(32)
    for (int k = warp; k < LL; k += 8) {
        const float4* prow = (const float4*)(pos + ((size_t)bq * LL + k) * DD) + lane * 2;
        float4 p0 = prow[0], p1 = prow[1];
        float acc[8];
#pragma unroll
        for (int h = 0; h < 8; h++) {
            acc[h] = p0.x*wreg[h][0] + p0.y*wreg[h][1] + p0.z*wreg[h][2] + p0.w*wreg[h][3]
                   + p1.x*wreg[h][4] + p1.y*wreg[h][5] + p1.z*wreg[h][6] + p1.w*wreg[h][7];
        }
#pragma unroll
        for (int o = 16; o; o >>= 1) {
#pragma unroll
            for (int h = 0; h < 8; h++) acc[h] += __shfl_xor_sync(0xffffffffu, acc[h], o);
        }
        if (lane < 8) {
            float bd = acc[0];
#pragma unroll
            for (int h = 1; h < 8; h++) if (lane == h) bd = acc[h];
            float s = (bd + a_s[lane][k] + bias_s[lane]) * scale
                    - (1.0f - mask_s[k]) * 1e15f;
            g_scores[(((size_t)(b * HH + lane)) * LL + q) * LL + k] = s;
        }
    }
}

// ---------------- kernel 5: softmax + attn @ V + output transpose ----------------
// grid (B*H, 8), 256 threads. 48 q per CTA, 6 q per warp (blocked for V reuse).
// dynamic smem: V tile [384][32] (48KB) + probs [8 warps][6][384] (72KB).
__global__ __launch_bounds__(256) void softmax_av_kernel(float* __restrict__ out)
{
    extern __shared__ float sm[];
    float* val_s = sm;                // [384][32]
    float* probs = sm + LL * DH;      // [8][6][384]
    int bh = blockIdx.x;
    int b = bh >> 3, h = bh & 7;
    int q0 = blockIdx.y * 48;

    for (int idx = threadIdx.x; idx < LL * DH; idx += 256)
        val_s[idx] = g_vproj[(size_t)bh * (LL * DH) + idx];
    __syncthreads();

    int warp = threadIdx.x >> 5, lane = threadIdx.x & 31;
    float* pw = probs + warp * 6 * LL;
    float acc[6];

#pragma unroll
    for (int qq = 0; qq < 6; qq++) {
        int q = q0 + qq * 8 + warp;
        const float* srow = g_scores + ((size_t)bh * LL + q) * LL;
        float sv[12];
        float mx = -1e30f;
#pragma unroll
        for (int j = 0; j < 12; j++) { sv[j] = srow[j * 32 + lane]; mx = fmaxf(mx, sv[j]); }
#pragma unroll
        for (int o = 16; o; o >>= 1) mx = fmaxf(mx, __shfl_xor_sync(0xffffffffu, mx, o));
        float s = 0.f;
#pragma unroll
        for (int j = 0; j < 12; j++) { sv[j] = __expf(sv[j] - mx); s += sv[j]; }
#pragma unroll
        for (int o = 16; o; o >>= 1) s += __shfl_xor_sync(0xffffffffu, s, o);
        float inv = 1.0f / s;
#pragma unroll
        for (int j = 0; j < 12; j++) pw[qq * LL + j * 32 + lane] = sv[j] * inv;
        acc[qq] = 0.f;
    }
    __syncwarp();

    for (int k4 = 0; k4 < LL / 4; k4++) {
        float v0 = val_s[(k4 * 4 + 0) * DH + lane];
        float v1 = val_s[(k4 * 4 + 1) * DH + lane];
        float v2 = val_s[(k4 * 4 + 2) * DH + lane];
        float v3 = val_s[(k4 * 4 + 3) * DH + lane];
#pragma unroll
        for (int qq = 0; qq < 6; qq++) {
            float4 p = *(const float4*)(pw + qq * LL + k4 * 4);
            acc[qq] += p.x * v0 + p.y * v1 + p.z * v2 + p.w * v3;
        }
    }
#pragma unroll
    for (int qq = 0; qq < 6; qq++) {
        int q = q0 + qq * 8 + warp;
        out[((size_t)(b * LL + q)) * DD + h * DH + lane] = acc[qq];
    }
}

// ---------------- launch ----------------------------------------------------------
extern "C" void kernel_launch(void* const* d_in, const int* in_sizes, int n_in,
                              void* d_out, int out_size)
{
    const float* key   = (const float*)d_in[0];
    const float* query = (const float*)d_in[1];
    const float* value = (const float*)d_in[2];
    const float* pos   = (const float*)d_in[3];
    const float* mask  = (const float*)d_in[4];
    const float* Wk = (const float*)d_in[5];  const float* bk = (const float*)d_in[6];
    const float* Wq = (const float*)d_in[7];  const float* bq = (const float*)d_in[8];
    const float* Wv = (const float*)d_in[9];  const float* bv = (const float*)d_in[10];
    const float* Wr = (const float*)d_in[11]; const float* br = (const float*)d_in[12];
    const float* u  = (const float*)d_in[13]; const float* v  = (const float*)d_in[14];
    float* out = (float*)d_out;

    proj_kernel<<<dim3(12, 4), 256>>>(key,   Wk, bk, 0, nullptr, nullptr);
    proj_kernel<<<dim3(12, 4), 256>>>(query, Wq, bq, 1, u, v);
    proj_kernel<<<dim3(12, 4), 256>>>(value, Wv, bv, 2, nullptr, nullptr);
    wproj_kernel<<<dim3(BB * HH, 4), 256>>>(Wr, br);
    ac_kernel<<<dim3(BB * HH, 6, 6), 256>>>();
    score_kernel<<<BB * LL, 256>>>(pos, mask);

    const int dyn_smem = (LL * DH + 8 * 6 * LL) * (int)sizeof(float); // 122880
    cudaFuncSetAttribute(softmax_av_kernel,
                         cudaFuncAttributeMaxDynamicSharedMemorySize, dyn_smem);
    softmax_av_kernel<<<dim3(BB * HH, 8), 256, dyn_smem>>>(out);
}

// round 2
// speedup vs baseline: 1.3993x; 1.3993x over previous
#include <cuda_runtime.h>
#include <cuda_bf16.h>
#include <cstddef>

// Problem constants
#define BB 2
#define LL 384
#define DD 256
#define HH 8
#define DH 32

// ---------------- scratch (device globals; no allocation allowed) ----------------
__device__ float g_kproj[BB*HH*LL*DH];            // [b,h,l,dh]
__device__ float g_vproj[BB*HH*LL*DH];
__device__ float g_qu   [BB*HH*LL*DH];            // q + u
__device__ float g_qv   [BB*HH*LL*DH];            // q + v
__device__ float g_w    [(size_t)BB*HH*LL*DD];    // [b,h,q,din]
__device__ float g_bias [BB*HH*LL];               // [b,h,q]
__device__ float g_ac   [(size_t)BB*HH*LL*LL];    // A_C scores [b,h,q,k]
__device__ float g_scores[(size_t)BB*HH*LL*LL];   // final scores [b,h,q,k]

// ---------------- kernel 1: QKV projections (x @ W.T + b), remap to [b,h,l,dh] --
__global__ __launch_bounds__(256) void proj_kernel(
    const float* __restrict__ x, const float* __restrict__ W,
    const float* __restrict__ bias, int mode,
    const float* __restrict__ uvec, const float* __restrict__ vvec)
{
    __shared__ float As[64][33];
    __shared__ float Bs[32][68];
    int m0 = blockIdx.x * 64, n0 = blockIdx.y * 64;
    int tid = threadIdx.x;
    int tx = tid & 15, ty = tid >> 4;
    float acc[4][4];
#pragma unroll
    for (int i = 0; i < 4; i++)
#pragma unroll
        for (int j = 0; j < 4; j++) acc[i][j] = 0.f;

    for (int k0 = 0; k0 < DD; k0 += 32) {
        for (int idx = tid; idx < 2048; idx += 256) {
            int r = idx >> 5, c = idx & 31;
            As[r][c] = x[(m0 + r) * DD + k0 + c];
        }
        for (int idx = tid; idx < 2048; idx += 256) {
            int n = idx >> 5, kk = idx & 31;
            Bs[kk][n] = W[(n0 + n) * DD + k0 + kk];
        }
        __syncthreads();
#pragma unroll
        for (int kk = 0; kk < 32; kk++) {
            float a0 = As[ty*4+0][kk], a1 = As[ty*4+1][kk];
            float a2 = As[ty*4+2][kk], a3 = As[ty*4+3][kk];
            float4 bb = *(const float4*)&Bs[kk][tx*4];
            acc[0][0] += a0*bb.x; acc[0][1] += a0*bb.y; acc[0][2] += a0*bb.z; acc[0][3] += a0*bb.w;
            acc[1][0] += a1*bb.x; acc[1][1] += a1*bb.y; acc[1][2] += a1*bb.z; acc[1][3] += a1*bb.w;
            acc[2][0] += a2*bb.x; acc[2][1] += a2*bb.y; acc[2][2] += a2*bb.z; acc[2][3] += a2*bb.w;
            acc[3][0] += a3*bb.x; acc[3][1] += a3*bb.y; acc[3][2] += a3*bb.z; acc[3][3] += a3*bb.w;
        }
        __syncthreads();
    }
#pragma unroll
    for (int i = 0; i < 4; i++) {
        int m = m0 + ty*4 + i;
        int b = m / LL, l = m - b * LL;
#pragma unroll
        for (int j = 0; j < 4; j++) {
            int n = n0 + tx*4 + j;
            int h = n >> 5, dh = n & 31;
            float val = acc[i][j] + bias[n];
            size_t o = (((size_t)b * HH + h) * LL + l) * DH + dh;
            if (mode == 0)      g_kproj[o] = val;
            else if (mode == 2) g_vproj[o] = val;
            else { g_qu[o] = val + uvec[n]; g_qv[o] = val + vvec[n]; }
        }
    }
}

// ---------------- kernel 2: w[b,h,q,:] = qv[b,h,q,:] @ Wr_h  (proper GEMM) -------
// grid (B*H, 6, 4), 256 threads. Output tile 64q x 64c, K=32 single chunk.
__global__ __launch_bounds__(256) void wproj_gemm_kernel(const float* __restrict__ Wr)
{
    __shared__ float As[64][33];   // qv tile [q][dh]
    __shared__ float Bs[32][68];   // Wr_h slice [dh][c]
    int bh = blockIdx.x;
    int h  = bh & (HH - 1);
    int q0 = blockIdx.y * 64, c0 = blockIdx.z * 64;
    int tid = threadIdx.x, tx = tid & 15, ty = tid >> 4;

    for (int idx = tid; idx < 2048; idx += 256) {
        int r = idx >> 5, c = idx & 31;
        As[r][c] = g_qv[((size_t)bh * LL + q0 + r) * DH + c];
    }
    for (int idx = tid; idx < 2048; idx += 256) {
        int dh = idx >> 6, c = idx & 63;
        Bs[dh][c] = Wr[(h * DH + dh) * DD + c0 + c];
    }
    __syncthreads();

    float acc[4][4];
#pragma unroll
    for (int i = 0; i < 4; i++)
#pragma unroll
        for (int j = 0; j < 4; j++) acc[i][j] = 0.f;
#pragma unroll
    for (int dh = 0; dh < 32; dh++) {
        float a0 = As[ty*4+0][dh], a1 = As[ty*4+1][dh];
        float a2 = As[ty*4+2][dh], a3 = As[ty*4+3][dh];
        float4 bb = *(const float4*)&Bs[dh][tx*4];
        acc[0][0] += a0*bb.x; acc[0][1] += a0*bb.y; acc[0][2] += a0*bb.z; acc[0][3] += a0*bb.w;
        acc[1][0] += a1*bb.x; acc[1][1] += a1*bb.y; acc[1][2] += a1*bb.z; acc[1][3] += a1*bb.w;
        acc[2][0] += a2*bb.x; acc[2][1] += a2*bb.y; acc[2][2] += a2*bb.z; acc[2][3] += a2*bb.w;
        acc[3][0] += a3*bb.x; acc[3][1] += a3*bb.y; acc[3][2] += a3*bb.z; acc[3][3] += a3*bb.w;
    }
#pragma unroll
    for (int i = 0; i < 4; i++)
#pragma unroll
        for (int j = 0; j < 4; j++)
            g_w[((size_t)bh * LL + q0 + ty*4 + i) * DD + c0 + tx*4 + j] = acc[i][j];
}

// ---------------- kernel 2b: bias[b,h,q] = qv . br_h  ---------------------------
// grid (B*H), 256 threads (8 warps). Warp handles q = warp, warp+8, ... lane = dh.
__global__ __launch_bounds__(256) void bias_kernel(const float* __restrict__ br)
{
    int bh = blockIdx.x;
    int h  = bh & (HH - 1);
    int warp = threadIdx.x >> 5, lane = threadIdx.x & 31;
    float brv = br[h * DH + lane];
    for (int q = warp; q < LL; q += 8) {
        float p = g_qv[((size_t)bh * LL + q) * DH + lane] * brv;
#pragma unroll
        for (int o = 16; o; o >>= 1) p += __shfl_xor_sync(0xffffffffu, p, o);
        if (lane == 0) g_bias[bh * LL + q] = p;
    }
}

// ---------------- kernel 3: A_C[b,h,q,k] = (q+u) . k  (batched 384x384x32) -------
__global__ __launch_bounds__(256) void ac_kernel()
{
    __shared__ float As[64][33];
    __shared__ float Bs[32][68];
    int bh = blockIdx.x;
    int q0 = blockIdx.y * 64, k0 = blockIdx.z * 64;
    int tid = threadIdx.x, tx = tid & 15, ty = tid >> 4;
    for (int idx = tid; idx < 2048; idx += 256) {
        int r = idx >> 5, c = idx & 31;
        As[r][c] = g_qu[(size_t)bh * (LL * DH) + (q0 + r) * DH + c];
    }
    for (int idx = tid; idx < 2048; idx += 256) {
        int n = idx >> 5, d = idx & 31;
        Bs[d][n] = g_kproj[(size_t)bh * (LL * DH) + (k0 + n) * DH + d];
    }
    __syncthreads();
    float acc[4][4];
#pragma unroll
    for (int i = 0; i < 4; i++)
#pragma unroll
        for (int j = 0; j < 4; j++) acc[i][j] = 0.f;
#pragma unroll
    for (int d = 0; d < 32; d++) {
        float a0 = As[ty*4+0][d], a1 = As[ty*4+1][d];
        float a2 = As[ty*4+2][d], a3 = As[ty*4+3][d];
        float4 bb = *(const float4*)&Bs[d][tx*4];
        acc[0][0] += a0*bb.x; acc[0][1] += a0*bb.y; acc[0][2] += a0*bb.z; acc[0][3] += a0*bb.w;
        acc[1][0] += a1*bb.x; acc[1][1] += a1*bb.y; acc[1][2] += a1*bb.z; acc[1][3] += a1*bb.w;
        acc[2][0] += a2*bb.x; acc[2][1] += a2*bb.y; acc[2][2] += a2*bb.z; acc[2][3] += a2*bb.w;
        acc[3][0] += a3*bb.x; acc[3][1] += a3*bb.y; acc[3][2] += a3*bb.z; acc[3][3] += a3*bb.w;
    }
#pragma unroll
    for (int i = 0; i < 4; i++)
#pragma unroll
        for (int j = 0; j < 4; j++)
            g_ac[(size_t)bh * (LL * LL) + (size_t)(q0 + ty*4 + i) * LL + (k0 + tx*4 + j)]
                = acc[i][j];
}

// ---------------- kernel 4 (DOMINANT): stream pos, produce final scores ----------
// score[b,h,q,k] = (pos[b,q,k,:].w[b,h,q,:] + A_C + bias)*scale - (1-mask)*1e15
// grid (B*L), 256 threads. Warp w handles contiguous k in [w*48, w*48+48).
// Reduction: value-halving lane exchange (9 SHFL per k, vs 40 for full butterfly).
#define SPAD 385

__device__ __forceinline__ float reduce8heads(const float acc[8], int lane)
{
    // After: every lane in group {4h..4h+3} holds the full 32-lane sum for
    // head h = (lane>>2)&7.
    bool hi16 = (lane & 16) != 0;
    float v[4];
#pragma unroll
    for (int j = 0; j < 4; j++) {
        float keep = hi16 ? acc[j+4] : acc[j];
        float send = hi16 ? acc[j]   : acc[j+4];
        v[j] = keep + __shfl_xor_sync(0xffffffffu, send, 16);
    }
    bool hi8 = (lane & 8) != 0;
    float w0, w1;
    {
        float keep = hi8 ? v[2] : v[0];
        float send = hi8 ? v[0] : v[2];
        w0 = keep + __shfl_xor_sync(0xffffffffu, send, 8);
        keep = hi8 ? v[3] : v[1];
        send = hi8 ? v[1] : v[3];
        w1 = keep + __shfl_xor_sync(0xffffffffu, send, 8);
    }
    bool hi4 = (lane & 4) != 0;
    float keep = hi4 ? w1 : w0;
    float send = hi4 ? w0 : w1;
    float x = keep + __shfl_xor_sync(0xffffffffu, send, 4);
    x += __shfl_xor_sync(0xffffffffu, x, 2);
    x += __shfl_xor_sync(0xffffffffu, x, 1);
    return x;
}

__global__ __launch_bounds__(256) void score_kernel(
    const float* __restrict__ pos, const float* __restrict__ key_mask)
{
    int bq = blockIdx.x;
    int b = bq / LL, q = bq - b * LL;
    __shared__ float a_s[HH * SPAD];   // A_C + bias - mask_penalty/scale
    __shared__ float s_out[HH * SPAD];
    int tid = threadIdx.x;

    // fused additive term: score = (bd + a_s) * scale
    const float inv_scale_pen = 5.656854249492381e15f; // 1e15 / (1/sqrt(32))
    for (int idx = tid; idx < HH * LL; idx += 256) {
        int h = idx / LL, k = idx - h * LL;
        a_s[h * SPAD + k] =
            g_ac[(size_t)(b * HH + h) * (LL * LL) + (size_t)q * LL + k]
          + g_bias[(b * HH + h) * LL + q]
          - (1.0f - key_mask[b * LL + k]) * inv_scale_pen;
    }

    int warp = tid >> 5, lane = tid & 31;
    // per-lane registers: w[h][din], din = lane*8 .. lane*8+7
    float wreg[8][8];
#pragma unroll
    for (int h = 0; h < 8; h++) {
        const float4* wp = (const float4*)(g_w + (((size_t)(b * HH + h)) * LL + q) * DD) + lane * 2;
        float4 w0 = wp[0], w1 = wp[1];
        wreg[h][0]=w0.x; wreg[h][1]=w0.y; wreg[h][2]=w0.z; wreg[h][3]=w0.w;
        wreg[h][4]=w1.x; wreg[h][5]=w1.y; wreg[h][6]=w1.z; wreg[h][7]=w1.w;
    }
    __syncthreads();

    const float scale = 0.17677669529663687f; // 1/sqrt(32)
    const float4* pbase = (const float4*)(pos + (size_t)bq * LL * DD) + lane * 2;
    int hme = (lane >> 2) & 7;
    bool writer = (lane & 3) == 0;

    int k0 = warp * 48;
    for (int i = 0; i < 48; i += 2) {
        int k = k0 + i;
        const float4* pA = pbase + (size_t)k * 64;
        float4 a0 = pA[0],  a1 = pA[1];
        float4 b0 = pA[64], b1 = pA[65];
        float accA[8], accB[8];
#pragma unroll
        for (int h = 0; h < 8; h++) {
            accA[h] = a0.x*wreg[h][0] + a0.y*wreg[h][1] + a0.z*wreg[h][2] + a0.w*wreg[h][3]
                    + a1.x*wreg[h][4] + a1.y*wreg[h][5] + a1.z*wreg[h][6] + a1.w*wreg[h][7];
            accB[h] = b0.x*wreg[h][0] + b0.y*wreg[h][1] + b0.z*wreg[h][2] + b0.w*wreg[h][3]
                    + b1.x*wreg[h][4] + b1.y*wreg[h][5] + b1.z*wreg[h][6] + b1.w*wreg[h][7];
        }
        float xA = reduce8heads(accA, lane);
        float xB = reduce8heads(accB, lane);
        if (writer) {
            s_out[hme * SPAD + k]     = (xA + a_s[hme * SPAD + k])     * scale;
            s_out[hme * SPAD + k + 1] = (xB + a_s[hme * SPAD + k + 1]) * scale;
        }
    }
    __syncthreads();
    // coalesced write-out
    for (int idx = tid; idx < HH * LL; idx += 256) {
        int h = idx / LL, k = idx - h * LL;
        g_scores[(((size_t)(b * HH + h)) * LL + q) * LL + k] = s_out[h * SPAD + k];
    }
}

// ---------------- kernel 5: softmax + attn @ V + output transpose ----------------
__global__ __launch_bounds__(256) void softmax_av_kernel(float* __restrict__ out)
{
    extern __shared__ float sm[];
    float* val_s = sm;                // [384][32]
    float* probs = sm + LL * DH;      // [8][6][384]
    int bh = blockIdx.x;
    int b = bh >> 3, h = bh & 7;
    int q0 = blockIdx.y * 48;

    for (int idx = threadIdx.x; idx < LL * DH; idx += 256)
        val_s[idx] = g_vproj[(size_t)bh * (LL * DH) + idx];
    __syncthreads();

    int warp = threadIdx.x >> 5, lane = threadIdx.x & 31;
    float* pw = probs + warp * 6 * LL;
    float acc[6];

#pragma unroll
    for (int qq = 0; qq < 6; qq++) {
        int q = q0 + qq * 8 + warp;
        const float* srow = g_scores + ((size_t)bh * LL + q) * LL;
        float sv[12];
        float mx = -1e30f;
#pragma unroll
        for (int j = 0; j < 12; j++) { sv[j] = srow[j * 32 + lane]; mx = fmaxf(mx, sv[j]); }
#pragma unroll
        for (int o = 16; o; o >>= 1) mx = fmaxf(mx, __shfl_xor_sync(0xffffffffu, mx, o));
        float s = 0.f;
#pragma unroll
        for (int j = 0; j < 12; j++) { sv[j] = __expf(sv[j] - mx); s += sv[j]; }
#pragma unroll
        for (int o = 16; o; o >>= 1) s += __shfl_xor_sync(0xffffffffu, s, o);
        float inv = 1.0f / s;
#pragma unroll
        for (int j = 0; j < 12; j++) pw[qq * LL + j * 32 + lane] = sv[j] * inv;
        acc[qq] = 0.f;
    }
    __syncwarp();

    for (int k4 = 0; k4 < LL / 4; k4++) {
        float v0 = val_s[(k4 * 4 + 0) * DH + lane];
        float v1 = val_s[(k4 * 4 + 1) * DH + lane];
        float v2 = val_s[(k4 * 4 + 2) * DH + lane];
        float v3 = val_s[(k4 * 4 + 3) * DH + lane];
#pragma unroll
        for (int qq = 0; qq < 6; qq++) {
            float4 p = *(const float4*)(pw + qq * LL + k4 * 4);
            acc[qq] += p.x * v0 + p.y * v1 + p.z * v2 + p.w * v3;
        }
    }
#pragma unroll
    for (int qq = 0; qq < 6; qq++) {
        int q = q0 + qq * 8 + warp;
        out[((size_t)(b * LL + q)) * DD + h * DH + lane] = acc[qq];
    }
}

// ---------------- launch ----------------------------------------------------------
extern "C" void kernel_launch(void* const* d_in, const int* in_sizes, int n_in,
                              void* d_out, int out_size)
{
    const float* key   = (const float*)d_in[0];
    const float* query = (const float*)d_in[1];
    const float* value = (const float*)d_in[2];
    const float* pos   = (const float*)d_in[3];
    const float* mask  = (const float*)d_in[4];
    const float* Wk = (const float*)d_in[5];  const float* bk = (const float*)d_in[6];
    const float* Wq = (const float*)d_in[7];  const float* bq = (const float*)d_in[8];
    const float* Wv = (const float*)d_in[9];  const float* bv = (const float*)d_in[10];
    const float* Wr = (const float*)d_in[11]; const float* br = (const float*)d_in[12];
    const float* u  = (const float*)d_in[13]; const float* v  = (const float*)d_in[14];
    float* out = (float*)d_out;

    proj_kernel<<<dim3(12, 4), 256>>>(key,   Wk, bk, 0, nullptr, nullptr);
    proj_kernel<<<dim3(12, 4), 256>>>(query, Wq, bq, 1, u, v);
    proj_kernel<<<dim3(12, 4), 256>>>(value, Wv, bv, 2, nullptr, nullptr);
    wproj_gemm_kernel<<<dim3(BB * HH, 6, 4), 256>>>(Wr);
    bias_kernel<<<BB * HH, 256>>>(br);
    ac_kernel<<<dim3(BB * HH, 6, 6), 256>>>();
    score_kernel<<<BB * LL, 256>>>(pos, mask);

    const int dyn_smem = (LL * DH + 8 * 6 * LL) * (int)sizeof(float); // 122880
    cudaFuncSetAttribute(softmax_av_kernel,
                         cudaFuncAttributeMaxDynamicSharedMemorySize, dyn_smem);
    softmax_av_kernel<<<dim3(BB * HH, 8), 256, dyn_smem>>>(out);
}